// round 14
// baseline (speedup 1.0000x reference)
#include <cuda_runtime.h>
#include <math.h>

// SLIC superpixel k-means: 8 images of 224x224x3, K=100, 10 iterations + final assign.
// Output (float32): [labels (8*224*224)] ++ [mean_img (8*224*224*3)]
//
// R13 changes vs R11 (outputs bit-identical):
//  - TPB 128->256, PPT 4->2, same 32x16 tiles / 784 blocks: 42 warps/SM instead of
//    21. Occupancy was grid-limited (28%), kernel is latency-bound at issue=23% —
//    double the warp contexts to hide the LDG/ATOMS/rounded-fma chains.
//  - pixel LDGs hoisted above the center prologue (overlap ~600cyc img load with
//    prologue instead of serializing after the first barrier).

#define BATCH 8
#define H 224
#define W 224
#define HW (H * W)          // 50176
#define K 100
#define NITER 10
#define TPB 256
#define PPT 2
#define TILE_X 32
#define TILE_Y 16
#define NTX (W / TILE_X)    // 7
#define NTY (H / TILE_Y)    // 14
#define FIX_SCALE_F 67108864.0f           // 2^26 (exact in f32)
#define INV_FIX_F 1.4901161193847656e-8f  // 2^-26 (exact in f32)
#define MARGIN 2.0f

__device__ float g_ratio;
__device__ float g_cstore[NITER][BATCH][K][5];            // centers used at pass p (fallback chain)
__device__ unsigned long long g_acc[NITER][BATCH][K][6];  // per-pass fixed-point accumulators

// v >= 0; v*2^26 is an exact exponent shift in f32, then one rn-round to integer.
__device__ __forceinline__ unsigned long long fixp(float v) {
    return (unsigned long long)__float2ll_rn(v * FIX_SCALE_F);
}

// XLA-style sum of squares: each product rounded, then sequential adds (no fma)
__device__ __forceinline__ float sumsq5(float a, float b, float c, float d, float e) {
    float s = __fmul_rn(a, a);
    s = __fadd_rn(s, __fmul_rn(b, b));
    s = __fadd_rn(s, __fmul_rn(c, c));
    s = __fadd_rn(s, __fmul_rn(d, d));
    s = __fadd_rn(s, __fmul_rn(e, e));
    return s;
}

// GEMM-style k-chain: fma(a4,b4, fma(... fma(a1,b1, a0*b0)))
__device__ __forceinline__ float dot5(float a0, float a1, float a2, float a3, float a4,
                                      float b0, float b1, float b2, float b3, float b4) {
    float s = __fmul_rn(a0, b0);
    s = __fmaf_rn(a1, b1, s);
    s = __fmaf_rn(a2, b2, s);
    s = __fmaf_rn(a3, b3, s);
    s = __fmaf_rn(a4, b4, s);
    return s;
}

// --- init: ratio, grid centers into g_cstore[0], zero ALL accumulators ---
__global__ void slic_init_kernel(const float* __restrict__ img) {
    int b = blockIdx.x;
    int t = threadIdx.x;
    float ratio = (float)(10.0 / sqrt((double)HW / (double)K));  // f64 off hot path
    if (b == 0 && t == 0) g_ratio = ratio;
    if (t < K) {
        int gi = t / 10, gj = t % 10;
        int cy = (int)floor(((double)gi + 0.5) * (double)H / 10.0);
        int cx = (int)floor(((double)gj + 0.5) * (double)W / 10.0);
        int p = cy * W + cx;
        const float* px = img + ((size_t)b * HW + p) * 3;
        g_cstore[0][b][t][0] = __fmul_rn((float)cy, ratio);
        g_cstore[0][b][t][1] = __fmul_rn((float)cx, ratio);
        g_cstore[0][b][t][2] = px[0];
        g_cstore[0][b][t][3] = px[1];
        g_cstore[0][b][t][4] = px[2];
    }
    for (int it = 0; it < NITER; it++) {
        unsigned long long* acc = (unsigned long long*)g_acc[it][b];
        for (int i = t; i < K * 6; i += blockDim.x) acc[i] = 0ULL;
    }
}

// --- one pass: recompute centers, prune candidates, assign; accumulate or emit ---
__global__ __launch_bounds__(TPB) void slic_pass_kernel(
    const float* __restrict__ img, float* __restrict__ out, int iter)
{
    __shared__ float4 s_c[K * 2];    // all centers: (c0..c3), (c4, csq, -, -)
    __shared__ float4 s_cd[K * 2];   // candidates:  (c0..c3), (c4, csq, k_bits, -)
    __shared__ unsigned long long s_acc[K * 6];
    __shared__ unsigned s_bal[TPB / 32];
    __shared__ int s_ubi;
    __shared__ int s_ncand;

    const int b = blockIdx.z;
    const int t = threadIdx.x;
    const float ratio = g_ratio;

    // ---- pixel loads issued FIRST (overlap global latency with the prologue) ----
    const int ty0 = blockIdx.y * TILE_Y, tx0 = blockIdx.x * TILE_X;
    const int y = ty0 + (t >> 4);                 // 16 rows, 16 threads/row
    const int x0 = tx0 + (t & 15) * PPT;
    const float2* src = (const float2*)(img + ((size_t)b * HW + (size_t)y * W + x0) * 3);
    float2 a0 = src[0], a1 = src[1], a2 = src[2];

    if (t == 0) s_ubi = 0x7f7fffff;  // +FLT_MAX bits (positive floats: int order == float order)
    if (iter < NITER) {
        for (int i = t; i < K * 6; i += TPB) s_acc[i] = 0ULL;
    }

    // ---- centers (bit-identical in every block: pure f(exact integer accumulators)) ----
    if (t < K) {
        float c[5];
        if (iter == 0) {
#pragma unroll
            for (int i = 0; i < 5; i++) c[i] = g_cstore[0][b][t][i];
        } else {
            const unsigned long long* a = g_acc[iter - 1][b][t];
            unsigned long long cnt = a[5];
            if (cnt > 0ULL) {
                float den = fmaxf(__ll2float_rn((long long)cnt), 1.0f);
#pragma unroll
                for (int i = 0; i < 5; i++) {
                    // s64 -> f32 (one rn-round) then exact 2^-26 shift
                    float s = __ll2float_rn((long long)a[i]) * INV_FIX_F;
                    c[i] = __fdiv_rn(s, den);
                }
            } else {
#pragma unroll
                for (int i = 0; i < 5; i++) c[i] = g_cstore[iter - 1][b][t][i];
            }
        }
        float csq = sumsq5(c[0], c[1], c[2], c[3], c[4]);
        s_c[t * 2 + 0] = make_float4(c[0], c[1], c[2], c[3]);
        s_c[t * 2 + 1] = make_float4(c[4], csq, 0.0f, 0.0f);
        // designated block persists this pass's centers (empty-cluster fallback chain)
        if (iter >= 1 && iter < NITER && blockIdx.x == 0 && blockIdx.y == 0) {
#pragma unroll
            for (int i = 0; i < 5; i++) g_cstore[iter][b][t][i] = c[i];
        }
    }
    __syncthreads();

    // ---- candidate pruning: exact interval bounds on the tile's feature box ----
    const float fy_lo = __fmul_rn((float)ty0, ratio);
    const float fy_hi = __fmul_rn((float)(ty0 + TILE_Y - 1), ratio);
    const float fx_lo = __fmul_rn((float)tx0, ratio);
    const float fx_hi = __fmul_rn((float)(tx0 + TILE_X - 1), ratio);

    float lb = 0.0f;
    if (t < K) {
        float cy = s_c[t * 2].x, cx = s_c[t * 2].y;
        float dy = fmaxf(fmaxf(fy_lo - cy, cy - fy_hi), 0.0f);   // box distance
        float dx = fmaxf(fmaxf(fx_lo - cx, cx - fx_hi), 0.0f);
        lb = dy * dy + dx * dx;                                   // spatial lower bound
        float Dy = fmaxf(cy - fy_lo, fy_hi - cy);                 // max |c - endpoint|
        float Dx = fmaxf(cx - fx_lo, fx_hi - cx);
        float ub = Dy * Dy + Dx * Dx + 3.0f;                      // + max color dist^2
        atomicMin(&s_ubi, __float_as_int(ub));
    }
    __syncthreads();
    const float minub = __int_as_float(s_ubi);

    bool flag = (t < K) && (lb <= minub + MARGIN);
    unsigned bal = __ballot_sync(0xffffffffu, flag);
    int wrp = t >> 5;
    if ((t & 31) == 0) s_bal[wrp] = bal;
    __syncthreads();
    if (flag) {
        int pos = __popc(bal & ((1u << (t & 31)) - 1u));
#pragma unroll
        for (int w = 0; w < TPB / 32; w++)
            if (w < wrp) pos += __popc(s_bal[w]);
        s_cd[pos * 2 + 0] = s_c[t * 2 + 0];
        float4 v = s_c[t * 2 + 1];
        v.z = __int_as_float(t);                                  // original k
        s_cd[pos * 2 + 1] = v;
    }
    if (t == 0) {
        int n = 0;
#pragma unroll
        for (int w = 0; w < TPB / 32; w++) n += __popc(s_bal[w]);
        s_ncand = n;
    }
    __syncthreads();
    const int ncand = s_ncand;

    // ---- per-pixel features (colors already in registers) ----
    float cr[2] = {a0.x, a1.y};
    float cg[2] = {a0.y, a2.x};
    float cb[2] = {a1.x, a2.y};

    const float fy = __fmul_rn((float)y, ratio);
    float fx[2], fsq[2], bd[2];
    int bk[2];
#pragma unroll
    for (int j = 0; j < PPT; j++) {
        fx[j] = __fmul_rn((float)(x0 + j), ratio);
        fsq[j] = sumsq5(fy, fx[j], cr[j], cg[j], cb[j]);          // XLA rounding order
        bd[j] = 3.4e38f;
        bk[j] = 0;
    }

    // ---- argmin over candidates (ascending k; strict '<' = first-index tie-break) ----
    for (int i = 0; i < ncand; i++) {
        float4 ca = s_cd[i * 2 + 0];
        float4 cv = s_cd[i * 2 + 1];
        int k = __float_as_int(cv.z);
#pragma unroll
        for (int j = 0; j < PPT; j++) {
            float dot = dot5(fy, fx[j], cr[j], cg[j], cb[j],
                             ca.x, ca.y, ca.z, ca.w, cv.x);
            float d = __fsub_rn(__fadd_rn(fsq[j], cv.y), __fmul_rn(2.0f, dot));
            if (d < bd[j]) { bd[j] = d; bk[j] = k; }
        }
    }

    if (iter == NITER) {
        // ---- final outputs: labels (as f32) + superpixel-mean image ----
        float* lbl = out + (size_t)b * HW + (size_t)y * W + x0;
        ((float2*)lbl)[0] = make_float2((float)bk[0], (float)bk[1]);
        float* m = out + (size_t)BATCH * HW + ((size_t)b * HW + (size_t)y * W + x0) * 3;
        float v[6];
#pragma unroll
        for (int j = 0; j < PPT; j++) {
            float4 cc = s_c[bk[j] * 2 + 0];
            v[j * 3 + 0] = cc.z;
            v[j * 3 + 1] = cc.w;
            v[j * 3 + 2] = s_c[bk[j] * 2 + 1].x;
        }
        ((float2*)m)[0] = make_float2(v[0], v[1]);
        ((float2*)m)[1] = make_float2(v[2], v[3]);
        ((float2*)m)[2] = make_float2(v[4], v[5]);
    } else {
        // ---- exact fixed-point accumulation (integer: order-independent) ----
        if (bk[0] == bk[1]) {
            unsigned long long* a = &s_acc[bk[0] * 6];
            atomicAdd(&a[0], 2ULL * fixp(fy));
            atomicAdd(&a[1], fixp(fx[0]) + fixp(fx[1]));
            atomicAdd(&a[2], fixp(cr[0]) + fixp(cr[1]));
            atomicAdd(&a[3], fixp(cg[0]) + fixp(cg[1]));
            atomicAdd(&a[4], fixp(cb[0]) + fixp(cb[1]));
            atomicAdd(&a[5], 2ULL);
        } else {
#pragma unroll
            for (int j = 0; j < PPT; j++) {
                unsigned long long* a = &s_acc[bk[j] * 6];
                atomicAdd(&a[0], fixp(fy));
                atomicAdd(&a[1], fixp(fx[j]));
                atomicAdd(&a[2], fixp(cr[j]));
                atomicAdd(&a[3], fixp(cg[j]));
                atomicAdd(&a[4], fixp(cb[j]));
                atomicAdd(&a[5], 1ULL);
            }
        }
        __syncthreads();
        unsigned long long* gacc = (unsigned long long*)g_acc[iter][b];
        for (int i = t; i < K * 6; i += TPB) {
            unsigned long long v = s_acc[i];
            if (v) atomicAdd(&gacc[i], v);    // integer: exact & order-independent
        }
    }
}

extern "C" void kernel_launch(void* const* d_in, const int* in_sizes, int n_in,
                              void* d_out, int out_size)
{
    const float* img = (const float*)d_in[0];
    float* out = (float*)d_out;
    (void)in_sizes; (void)n_in; (void)out_size;

    slic_init_kernel<<<BATCH, 256>>>(img);

    dim3 grid(NTX, NTY, BATCH);
    for (int p = 0; p <= NITER; ++p) {
        slic_pass_kernel<<<grid, TPB>>>(img, out, p);
    }
}

// round 16
// speedup vs baseline: 1.6742x; 1.6742x over previous
#include <cuda_runtime.h>
#include <math.h>

// SLIC superpixel k-means: 8 images of 224x224x3, K=100, 10 iterations + final assign.
// Output (float32): [labels (8*224*224)] ++ [mean_img (8*224*224*3)]
//
// R15 == R14 resubmitted (R14 bench was an infra failure: container died twice,
// kernel never evaluated).
//
// R14 theory vs R11 (outputs bit-identical):
//  - Issued-instruction accounting across R11/R13 shows per-WARP overhead (~2300
//    instr) dominates; per-pixel math is ~15% of issue. So: fewest possible warps.
//    TILE 32x32, TPB=128, PPT=8 -> 392 blocks, 1568 warps (R11 had 3136, R13 6272).
//    ILP from 8 independent pixel chains replaces occupancy for latency hiding
//    (R11 already proved 2.65 blocks/SM suffices).
//  - RLE accumulation over 8 pixels halves ATOMS per pixel.

#define BATCH 8
#define H 224
#define W 224
#define HW (H * W)          // 50176
#define K 100
#define NITER 10
#define TPB 128
#define PPT 8
#define TILE 32             // 32x32 pixel tile
#define NT (W / TILE)       // 7
#define FIX_SCALE_F 67108864.0f           // 2^26 (exact in f32)
#define INV_FIX_F 1.4901161193847656e-8f  // 2^-26 (exact in f32)
#define MARGIN 2.0f

__device__ float g_ratio;
__device__ float g_cstore[NITER][BATCH][K][5];            // centers used at pass p (fallback chain)
__device__ unsigned long long g_acc[NITER][BATCH][K][6];  // per-pass fixed-point accumulators

// v >= 0; v*2^26 is an exact exponent shift in f32, then one rn-round to integer.
__device__ __forceinline__ unsigned long long fixp(float v) {
    return (unsigned long long)__float2ll_rn(v * FIX_SCALE_F);
}

// XLA-style sum of squares: each product rounded, then sequential adds (no fma)
__device__ __forceinline__ float sumsq5(float a, float b, float c, float d, float e) {
    float s = __fmul_rn(a, a);
    s = __fadd_rn(s, __fmul_rn(b, b));
    s = __fadd_rn(s, __fmul_rn(c, c));
    s = __fadd_rn(s, __fmul_rn(d, d));
    s = __fadd_rn(s, __fmul_rn(e, e));
    return s;
}

// GEMM-style k-chain: fma(a4,b4, fma(... fma(a1,b1, a0*b0)))
__device__ __forceinline__ float dot5(float a0, float a1, float a2, float a3, float a4,
                                      float b0, float b1, float b2, float b3, float b4) {
    float s = __fmul_rn(a0, b0);
    s = __fmaf_rn(a1, b1, s);
    s = __fmaf_rn(a2, b2, s);
    s = __fmaf_rn(a3, b3, s);
    s = __fmaf_rn(a4, b4, s);
    return s;
}

// --- init: ratio, grid centers into g_cstore[0], zero ALL accumulators ---
__global__ void slic_init_kernel(const float* __restrict__ img) {
    int b = blockIdx.x;
    int t = threadIdx.x;
    float ratio = (float)(10.0 / sqrt((double)HW / (double)K));  // f64 off hot path
    if (b == 0 && t == 0) g_ratio = ratio;
    if (t < K) {
        int gi = t / 10, gj = t % 10;
        int cy = (int)floor(((double)gi + 0.5) * (double)H / 10.0);
        int cx = (int)floor(((double)gj + 0.5) * (double)W / 10.0);
        int p = cy * W + cx;
        const float* px = img + ((size_t)b * HW + p) * 3;
        g_cstore[0][b][t][0] = __fmul_rn((float)cy, ratio);
        g_cstore[0][b][t][1] = __fmul_rn((float)cx, ratio);
        g_cstore[0][b][t][2] = px[0];
        g_cstore[0][b][t][3] = px[1];
        g_cstore[0][b][t][4] = px[2];
    }
    for (int it = 0; it < NITER; it++) {
        unsigned long long* acc = (unsigned long long*)g_acc[it][b];
        for (int i = t; i < K * 6; i += blockDim.x) acc[i] = 0ULL;
    }
}

// --- one pass: recompute centers, prune candidates, assign; accumulate or emit ---
__global__ __launch_bounds__(TPB) void slic_pass_kernel(
    const float* __restrict__ img, float* __restrict__ out, int iter)
{
    __shared__ float4 s_c[K * 2];    // all centers: (c0..c3), (c4, csq, -, -)
    __shared__ float4 s_cd[K * 2];   // candidates:  (c0..c3), (c4, csq, k_bits, -)
    __shared__ unsigned long long s_acc[K * 6];
    __shared__ unsigned s_bal[TPB / 32];
    __shared__ int s_ubi;
    __shared__ int s_ncand;

    const int b = blockIdx.z;
    const int t = threadIdx.x;
    const float ratio = g_ratio;

    // ---- pixel loads FIRST (overlap global latency with the prologue) ----
    // 128 threads, 32x32 tile, 8 px/thread: 4 threads/row, 32 rows
    const int ty0 = blockIdx.y * TILE, tx0 = blockIdx.x * TILE;
    const int y = ty0 + (t >> 2);
    const int x0 = tx0 + (t & 3) * PPT;
    const float4* src = (const float4*)(img + ((size_t)b * HW + (size_t)y * W + x0) * 3);
    float pix[24];   // 8 px * rgb
#pragma unroll
    for (int q = 0; q < 6; q++) {
        float4 v = src[q];
        pix[q * 4 + 0] = v.x; pix[q * 4 + 1] = v.y;
        pix[q * 4 + 2] = v.z; pix[q * 4 + 3] = v.w;
    }

    if (t == 0) s_ubi = 0x7f7fffff;  // +FLT_MAX bits
    if (iter < NITER) {
        for (int i = t; i < K * 6; i += TPB) s_acc[i] = 0ULL;
    }

    // ---- centers (bit-identical in every block: pure f(exact integer accumulators)) ----
    if (t < K) {
        float c[5];
        if (iter == 0) {
#pragma unroll
            for (int i = 0; i < 5; i++) c[i] = g_cstore[0][b][t][i];
        } else {
            const unsigned long long* a = g_acc[iter - 1][b][t];
            unsigned long long cnt = a[5];
            if (cnt > 0ULL) {
                float den = fmaxf(__ll2float_rn((long long)cnt), 1.0f);
#pragma unroll
                for (int i = 0; i < 5; i++) {
                    float s = __ll2float_rn((long long)a[i]) * INV_FIX_F;  // exact shift
                    c[i] = __fdiv_rn(s, den);
                }
            } else {
#pragma unroll
                for (int i = 0; i < 5; i++) c[i] = g_cstore[iter - 1][b][t][i];
            }
        }
        float csq = sumsq5(c[0], c[1], c[2], c[3], c[4]);
        s_c[t * 2 + 0] = make_float4(c[0], c[1], c[2], c[3]);
        s_c[t * 2 + 1] = make_float4(c[4], csq, 0.0f, 0.0f);
        // designated block persists this pass's centers (empty-cluster fallback chain)
        if (iter >= 1 && iter < NITER && blockIdx.x == 0 && blockIdx.y == 0) {
#pragma unroll
            for (int i = 0; i < 5; i++) g_cstore[iter][b][t][i] = c[i];
        }
    }
    __syncthreads();

    // ---- candidate pruning: exact interval bounds on the tile's feature box ----
    const float fy_lo = __fmul_rn((float)ty0, ratio);
    const float fy_hi = __fmul_rn((float)(ty0 + TILE - 1), ratio);
    const float fx_lo = __fmul_rn((float)tx0, ratio);
    const float fx_hi = __fmul_rn((float)(tx0 + TILE - 1), ratio);

    float lb = 0.0f;
    if (t < K) {
        float cy = s_c[t * 2].x, cx = s_c[t * 2].y;
        float dy = fmaxf(fmaxf(fy_lo - cy, cy - fy_hi), 0.0f);   // box distance
        float dx = fmaxf(fmaxf(fx_lo - cx, cx - fx_hi), 0.0f);
        lb = dy * dy + dx * dx;                                   // spatial lower bound
        float Dy = fmaxf(cy - fy_lo, fy_hi - cy);                 // max |c - endpoint|
        float Dx = fmaxf(cx - fx_lo, fx_hi - cx);
        float ub = Dy * Dy + Dx * Dx + 3.0f;                      // + max color dist^2
        atomicMin(&s_ubi, __float_as_int(ub));
    }
    __syncthreads();
    const float minub = __int_as_float(s_ubi);

    bool flag = (t < K) && (lb <= minub + MARGIN);
    unsigned bal = __ballot_sync(0xffffffffu, flag);
    int wrp = t >> 5;
    if ((t & 31) == 0) s_bal[wrp] = bal;
    __syncthreads();
    if (flag) {
        int pos = __popc(bal & ((1u << (t & 31)) - 1u));
#pragma unroll
        for (int w = 0; w < TPB / 32; w++)
            if (w < wrp) pos += __popc(s_bal[w]);
        s_cd[pos * 2 + 0] = s_c[t * 2 + 0];
        float4 v = s_c[t * 2 + 1];
        v.z = __int_as_float(t);                                  // original k
        s_cd[pos * 2 + 1] = v;
    }
    if (t == 0) {
        int n = 0;
#pragma unroll
        for (int w = 0; w < TPB / 32; w++) n += __popc(s_bal[w]);
        s_ncand = n;
    }
    __syncthreads();
    const int ncand = s_ncand;

    // ---- per-pixel features ----
    const float fy = __fmul_rn((float)y, ratio);
    float fx[PPT], fsq[PPT], bd[PPT];
    int bk[PPT];
#pragma unroll
    for (int j = 0; j < PPT; j++) {
        fx[j] = __fmul_rn((float)(x0 + j), ratio);
        fsq[j] = sumsq5(fy, fx[j], pix[j * 3], pix[j * 3 + 1], pix[j * 3 + 2]);
        bd[j] = 3.4e38f;
        bk[j] = 0;
    }

    // ---- argmin over candidates (ascending k; strict '<' = first-index tie-break) ----
#pragma unroll 1
    for (int i = 0; i < ncand; i++) {
        float4 ca = s_cd[i * 2 + 0];
        float4 cv = s_cd[i * 2 + 1];
        int k = __float_as_int(cv.z);
#pragma unroll
        for (int j = 0; j < PPT; j++) {
            float dot = dot5(fy, fx[j], pix[j * 3], pix[j * 3 + 1], pix[j * 3 + 2],
                             ca.x, ca.y, ca.z, ca.w, cv.x);
            float d = __fsub_rn(__fadd_rn(fsq[j], cv.y), __fmul_rn(2.0f, dot));
            if (d < bd[j]) { bd[j] = d; bk[j] = k; }
        }
    }

    if (iter == NITER) {
        // ---- final outputs: labels (as f32) + superpixel-mean image ----
        float* lbl = out + (size_t)b * HW + (size_t)y * W + x0;
        ((float4*)lbl)[0] = make_float4((float)bk[0], (float)bk[1], (float)bk[2], (float)bk[3]);
        ((float4*)lbl)[1] = make_float4((float)bk[4], (float)bk[5], (float)bk[6], (float)bk[7]);
        float* m = out + (size_t)BATCH * HW + ((size_t)b * HW + (size_t)y * W + x0) * 3;
        float v[24];
#pragma unroll
        for (int j = 0; j < PPT; j++) {
            float4 cc = s_c[bk[j] * 2 + 0];
            v[j * 3 + 0] = cc.z;
            v[j * 3 + 1] = cc.w;
            v[j * 3 + 2] = s_c[bk[j] * 2 + 1].x;
        }
#pragma unroll
        for (int q = 0; q < 6; q++)
            ((float4*)m)[q] = make_float4(v[q * 4], v[q * 4 + 1], v[q * 4 + 2], v[q * 4 + 3]);
    } else {
        // ---- exact fixed-point accumulation, run-length compressed over 8 px ----
        int cur = bk[0];
        const unsigned long long fyq = fixp(fy);
        unsigned long long a0 = fyq, a1 = fixp(fx[0]);
        unsigned long long a2 = fixp(pix[0]), a3 = fixp(pix[1]), a4 = fixp(pix[2]);
        unsigned long long an = 1ULL;
#pragma unroll
        for (int j = 1; j < PPT; j++) {
            if (bk[j] == cur) {
                a0 += fyq; a1 += fixp(fx[j]);
                a2 += fixp(pix[j * 3]); a3 += fixp(pix[j * 3 + 1]); a4 += fixp(pix[j * 3 + 2]);
                an += 1ULL;
            } else {
                unsigned long long* a = &s_acc[cur * 6];
                atomicAdd(&a[0], a0); atomicAdd(&a[1], a1); atomicAdd(&a[2], a2);
                atomicAdd(&a[3], a3); atomicAdd(&a[4], a4); atomicAdd(&a[5], an);
                cur = bk[j];
                a0 = fyq; a1 = fixp(fx[j]);
                a2 = fixp(pix[j * 3]); a3 = fixp(pix[j * 3 + 1]); a4 = fixp(pix[j * 3 + 2]);
                an = 1ULL;
            }
        }
        {
            unsigned long long* a = &s_acc[cur * 6];
            atomicAdd(&a[0], a0); atomicAdd(&a[1], a1); atomicAdd(&a[2], a2);
            atomicAdd(&a[3], a3); atomicAdd(&a[4], a4); atomicAdd(&a[5], an);
        }
        __syncthreads();
        unsigned long long* gacc = (unsigned long long*)g_acc[iter][b];
        for (int i = t; i < K * 6; i += TPB) {
            unsigned long long v = s_acc[i];
            if (v) atomicAdd(&gacc[i], v);    // integer: exact & order-independent
        }
    }
}

extern "C" void kernel_launch(void* const* d_in, const int* in_sizes, int n_in,
                              void* d_out, int out_size)
{
    const float* img = (const float*)d_in[0];
    float* out = (float*)d_out;
    (void)in_sizes; (void)n_in; (void)out_size;

    slic_init_kernel<<<BATCH, 256>>>(img);

    dim3 grid(NT, NT, BATCH);   // 7 x 7 x 8 = 392 blocks
    for (int p = 0; p <= NITER; ++p) {
        slic_pass_kernel<<<grid, TPB>>>(img, out, p);
    }
}